// round 1
// baseline (speedup 1.0000x reference)
#include <cuda_runtime.h>

// Rayleigh–Bénard RHS: state [6, 256, 256, 128] f32 -> tendencies [6, 256, 256, 128] f32
// Layout: idx = ((f*NX + x)*NY + y)*NZ + z   (z contiguous)

namespace {
constexpr int NX = 256, NY = 256, NZ = 128;
constexpr int XS = NY * NZ;        // 32768
constexpr int FS = NX * XS;        // 8388608  (6*FS < 2^31, int indexing safe)

constexpr float CPc = 1004.0f, CVc = 717.0f;
constexpr float MUc = 1.8e-5f, KTHc = 0.025f, Gc = 9.8f;
constexpr float Rg  = CPc - CVc;   // 287

// spacings (computed in double, stored as float — matches numpy scalar path)
constexpr double DX = 1.0 / NX;
constexpr double DY = 1.0 / NY;
constexpr double DZ = 1.0 / (NZ - 1);

__constant__ float kInv2dx = (float)(0.5 / DX);
__constant__ float kInv2dy = (float)(0.5 / DY);
__constant__ float kInv2dz = (float)(0.5 / DZ);
__constant__ float kInvDx2 = (float)(1.0 / (DX * DX));
__constant__ float kInvDy2 = (float)(1.0 / (DY * DY));
__constant__ float kInvDz2 = (float)(1.0 / (DZ * DZ));

__global__ __launch_bounds__(512, 2)
void rb_kernel(const float* __restrict__ s, float* __restrict__ o)
{
    const int z = threadIdx.x;                       // 0..127
    const int y = (blockIdx.x << 2) | threadIdx.y;   // 4 y per block
    const int x = blockIdx.y;

    const int i0  = x * XS + y * NZ + z;
    const int ixm = ((x + NX - 1) & (NX - 1)) * XS + y * NZ + z;
    const int ixp = ((x + 1)      & (NX - 1)) * XS + y * NZ + z;
    const int iym = x * XS + ((y + NY - 1) & (NY - 1)) * NZ + z;
    const int iyp = x * XS + ((y + 1)      & (NY - 1)) * NZ + z;

    const bool lo = (z == 0);
    const bool hi = (z == NZ - 1);
    const bool interior = !(lo | hi);
    // clamped z neighbors (garbage at walls — outputs there are masked to 0)
    const int izm = i0 - (lo ? 0 : 1);
    const int izp = i0 + (hi ? 0 : 1);

#define LDF(f, i) __ldg(s + (f) * FS + (i))

    // centers
    const float uc = LDF(0, i0), vc = LDF(1, i0), wc = LDF(2, i0);
    const float rc = LDF(3, i0), Tc = LDF(4, i0), cc = LDF(5, i0);

    // x neighbors
    const float uxm = LDF(0, ixm), uxp = LDF(0, ixp);
    const float vxm = LDF(1, ixm), vxp = LDF(1, ixp);
    const float wxm = LDF(2, ixm), wxp = LDF(2, ixp);
    const float rxm = LDF(3, ixm), rxp = LDF(3, ixp);
    const float Txm = LDF(4, ixm), Txp = LDF(4, ixp);
    const float cxm = LDF(5, ixm), cxp = LDF(5, ixp);

    // y neighbors
    const float uym = LDF(0, iym), uyp = LDF(0, iyp);
    const float vym = LDF(1, iym), vyp = LDF(1, iyp);
    const float wym = LDF(2, iym), wyp = LDF(2, iyp);
    const float rym = LDF(3, iym), ryp = LDF(3, iyp);
    const float Tym = LDF(4, iym), Typ = LDF(4, iyp);
    const float cym = LDF(5, iym), cyp = LDF(5, iyp);

    // z neighbors (clamped at walls)
    const float uzm = LDF(0, izm), uzp = LDF(0, izp);
    const float vzm = LDF(1, izm), vzp = LDF(1, izp);
    const float wzm = LDF(2, izm), wzp = LDF(2, izp);
    const float rzm = LDF(3, izm), rzp = LDF(3, izp);
    const float Tzm = LDF(4, izm), Tzp = LDF(4, izp);
    const float czm = LDF(5, izm), czp = LDF(5, izp);

    const float inv2dx = kInv2dx, inv2dy = kInv2dy, inv2dz = kInv2dz;
    const float invdx2 = kInvDx2, invdy2 = kInvDy2, invdz2 = kInvDz2;

    // pressure gradient:  p = R * rou * T
    const float dpdx = Rg * (rxp * Txp - rxm * Txm) * inv2dx;
    const float dpdy = Rg * (ryp * Typ - rym * Tym) * inv2dy;
    const float dpdz = Rg * (rzp * Tzp - rzm * Tzm) * inv2dz;   // central (interior only matters)

    // continuity (x-flux only, matches reference)
    const float drou = -(rxp * uxp - rxm * uxm) * inv2dx;

    // laplacians (central z — interior only matters)
    const float lapU = (uxp + uxm - 2.0f * uc) * invdx2 + (uyp + uym - 2.0f * uc) * invdy2 + (uzp + uzm - 2.0f * uc) * invdz2;
    const float lapV = (vxp + vxm - 2.0f * vc) * invdx2 + (vyp + vym - 2.0f * vc) * invdy2 + (vzp + vzm - 2.0f * vc) * invdz2;
    const float lapW = (wxp + wxm - 2.0f * wc) * invdx2 + (wyp + wym - 2.0f * wc) * invdy2 + (wzp + wzm - 2.0f * wc) * invdz2;
    const float lapT = (Txp + Txm - 2.0f * Tc) * invdx2 + (Typ + Tym - 2.0f * Tc) * invdy2 + (Tzp + Tzm - 2.0f * Tc) * invdz2;

    // advection
    const float advU = uc * (uxp - uxm) * inv2dx + vc * (uyp - uym) * inv2dy + wc * (uzp - uzm) * inv2dz;
    const float advV = uc * (vxp - vxm) * inv2dx + vc * (vyp - vym) * inv2dy + wc * (vzp - vzm) * inv2dz;
    const float advW = uc * (wxp - wxm) * inv2dx + vc * (wyp - wym) * inv2dy + wc * (wzp - wzm) * inv2dz;
    const float advT = uc * (Txp - Txm) * inv2dx + vc * (Typ - Tym) * inv2dy + wc * (Tzp - Tzm) * inv2dz;

    // dc/dz: one-sided at walls, central interior
    float dcdz;
    if (lo)       dcdz = (-3.0f * cc + 4.0f * czp - __ldg(s + 5 * FS + i0 + 2)) * inv2dz;
    else if (hi)  dcdz = ( 3.0f * cc - 4.0f * czm + __ldg(s + 5 * FS + i0 - 2)) * inv2dz;
    else          dcdz = (czp - czm) * inv2dz;
    const float advC = uc * (cxp - cxm) * inv2dx + vc * (cyp - cym) * inv2dy + wc * dcdz;

    const float rinv = 1.0f / rc;
    const float du = (-dpdx + MUc * lapU) * rinv - advU;
    const float dv = (-dpdy + MUc * lapV) * rinv - advV;
    const float dw = (-Gc * rc - dpdz + MUc * lapW) * rinv - advW;
    const float dT = (KTHc * lapT) * rinv * (1.0f / CVc) - advT;
    const float dc = -advC;

    const float m = interior ? 1.0f : 0.0f;   // zero u,v,w,T tendencies at z walls
    o[0 * FS + i0] = du * m;
    o[1 * FS + i0] = dv * m;
    o[2 * FS + i0] = dw * m;
    o[3 * FS + i0] = drou;
    o[4 * FS + i0] = dT * m;
    o[5 * FS + i0] = dc;
#undef LDF
}
} // namespace

extern "C" void kernel_launch(void* const* d_in, const int* in_sizes, int n_in,
                              void* d_out, int out_size)
{
    const float* s = (const float*)d_in[0];
    float* o = (float*)d_out;
    dim3 block(NZ, 4, 1);             // 512 threads: full z-line × 4 y
    dim3 grid(NY / 4, NX, 1);         // 64 × 256 blocks
    rb_kernel<<<grid, block>>>(s, o);
}

// round 2
// speedup vs baseline: 1.2799x; 1.2799x over previous
#include <cuda_runtime.h>

namespace {
constexpr int NX = 256, NY = 256, NZ = 128;
constexpr int XS = NY * NZ;          // 32768 floats per x-plane per field
constexpr int FS = NX * XS;          // floats per field
constexpr int NZ4 = NZ / 4, XS4 = XS / 4, FS4 = FS / 4;

constexpr float CVc = 717.0f;
constexpr float MUc = 1.8e-5f, KTHc = 0.025f, Gc = 9.8f;
constexpr float Rg  = 287.0f;        // CP - CV

constexpr double DXd = 1.0 / NX, DYd = 1.0 / NY, DZd = 1.0 / (NZ - 1);
constexpr float inv2dx = (float)(0.5 / DXd);
constexpr float inv2dy = (float)(0.5 / DYd);
constexpr float inv2dz = (float)(0.5 / DZd);
constexpr float invdx2 = (float)(1.0 / (DXd * DXd));
constexpr float invdy2 = (float)(1.0 / (DYd * DYd));
constexpr float invdz2 = (float)(1.0 / (DZd * DZd));
constexpr float kTco   = KTHc / CVc;

__device__ __forceinline__ float4 operator+(float4 a, float4 b){ return make_float4(a.x+b.x, a.y+b.y, a.z+b.z, a.w+b.w); }
__device__ __forceinline__ float4 operator-(float4 a, float4 b){ return make_float4(a.x-b.x, a.y-b.y, a.z-b.z, a.w-b.w); }
__device__ __forceinline__ float4 operator*(float4 a, float4 b){ return make_float4(a.x*b.x, a.y*b.y, a.z*b.z, a.w*b.w); }
__device__ __forceinline__ float4 operator*(float4 a, float s){ return make_float4(a.x*s, a.y*s, a.z*s, a.w*s); }
__device__ __forceinline__ float4 operator*(float s, float4 a){ return a * s; }

// z-1 vector: {prev_lane.w, a.x, a.y, a.z}  (lane 0 edge value is garbage — masked)
__device__ __forceinline__ float4 zm_of(float4 a){
    float p = __shfl_up_sync(0xffffffffu, a.w, 1);
    return make_float4(p, a.x, a.y, a.z);
}
// z+1 vector: {a.y, a.z, a.w, next_lane.x}
__device__ __forceinline__ float4 zp_of(float4 a){
    float n = __shfl_down_sync(0xffffffffu, a.x, 1);
    return make_float4(a.y, a.z, a.w, n);
}

__device__ __forceinline__ float4 lap3(float4 c, float4 xm, float4 xp, float4 ym, float4 yp, float4 zm, float4 zp){
    return (xp + xm - c * 2.0f) * invdx2 + (yp + ym - c * 2.0f) * invdy2 + (zp + zm - c * 2.0f) * invdz2;
}
__device__ __forceinline__ float4 adv3(float4 u, float4 v, float4 w, float4 xm, float4 xp, float4 ym, float4 yp, float4 zm, float4 zp){
    return u * ((xp - xm) * inv2dx) + v * ((yp - ym) * inv2dy) + w * ((zp - zm) * inv2dz);
}

__global__ __launch_bounds__(256, 2)
void rb4_kernel(const float4* __restrict__ s, float4* __restrict__ o)
{
    const int lane = threadIdx.x;                       // 0..31 : z chunk (4 z per lane)
    const int y = (blockIdx.x << 3) | threadIdx.y;      // 8 y per block
    const int x = blockIdx.y;

    const int rowc = y * NZ4 + lane;
    const int ic  = x * XS4 + rowc;
    const int ixm = ((x + NX - 1) & (NX - 1)) * XS4 + rowc;
    const int ixp = ((x + 1)      & (NX - 1)) * XS4 + rowc;
    const int iym = x * XS4 + ((y + NY - 1) & (NY - 1)) * NZ4 + lane;
    const int iyp = x * XS4 + ((y + 1)      & (NY - 1)) * NZ4 + lane;

    // wall mask: z==0 is lane0.elem0 ; z==127 is lane31.elem3
    const float4 m = make_float4(lane == 0 ? 0.0f : 1.0f, 1.0f, 1.0f, lane == 31 ? 0.0f : 1.0f);

    // ---- centers & 1/rho ----
    const float4 uc = s[0 * FS4 + ic];
    const float4 vc = s[1 * FS4 + ic];
    const float4 wc = s[2 * FS4 + ic];
    const float4 rc = s[3 * FS4 + ic];
    const float4 rinv = make_float4(1.0f / rc.x, 1.0f / rc.y, 1.0f / rc.z, 1.0f / rc.w);

    // ---- phase 1: rho & T  → pressure gradient, dT, (keep rxm/rxp for drou) ----
    const float4 rxm = s[3 * FS4 + ixm], rxp = s[3 * FS4 + ixp];
    const float4 rym = s[3 * FS4 + iym], ryp = s[3 * FS4 + iyp];
    const float4 rzm = zm_of(rc), rzp = zp_of(rc);
    (void)rym; (void)ryp; // loaded for symmetry of L2 pattern? no — drop them entirely
    const float4 Tc  = s[4 * FS4 + ic];
    const float4 Txm = s[4 * FS4 + ixm], Txp = s[4 * FS4 + ixp];
    const float4 Tym = s[4 * FS4 + iym], Typ = s[4 * FS4 + iyp];
    const float4 Tzm = zm_of(Tc), Tzp = zp_of(Tc);

    const float4 dpdx = (rxp * Txp - rxm * Txm) * (Rg * inv2dx);
    const float4 dpdy = (ryp * Typ - rym * Tym) * (Rg * inv2dy);
    const float4 dpdz = (rzp * Tzp - rzm * Tzm) * (Rg * inv2dz);

    {
        const float4 lapT = lap3(Tc, Txm, Txp, Tym, Typ, Tzm, Tzp);
        const float4 advT = adv3(uc, vc, wc, Txm, Txp, Tym, Typ, Tzm, Tzp);
        const float4 dT = (lapT * kTco) * rinv - advT;
        o[4 * FS4 + ic] = dT * m;
    }

    // ---- phase 2: u  (+ drou, which needs rho & u at x±) ----
    {
        const float4 uxm = s[0 * FS4 + ixm], uxp = s[0 * FS4 + ixp];
        const float4 uym = s[0 * FS4 + iym], uyp = s[0 * FS4 + iyp];
        const float4 uzm = zm_of(uc), uzp = zp_of(uc);

        const float4 drou = (rxm * uxm - rxp * uxp) * inv2dx;
        o[3 * FS4 + ic] = drou;

        const float4 lapU = lap3(uc, uxm, uxp, uym, uyp, uzm, uzp);
        const float4 advU = adv3(uc, vc, wc, uxm, uxp, uym, uyp, uzm, uzp);
        const float4 du = (lapU * MUc - dpdx) * rinv - advU;
        o[0 * FS4 + ic] = du * m;
    }

    // ---- phase 3: v ----
    {
        const float4 vxm = s[1 * FS4 + ixm], vxp = s[1 * FS4 + ixp];
        const float4 vym = s[1 * FS4 + iym], vyp = s[1 * FS4 + iyp];
        const float4 vzm = zm_of(vc), vzp = zp_of(vc);
        const float4 lapV = lap3(vc, vxm, vxp, vym, vyp, vzm, vzp);
        const float4 advV = adv3(uc, vc, wc, vxm, vxp, vym, vyp, vzm, vzp);
        const float4 dv = (lapV * MUc - dpdy) * rinv - advV;
        o[1 * FS4 + ic] = dv * m;
    }

    // ---- phase 4: w   ((-G*rho)/rho == -G) ----
    {
        const float4 wxm = s[2 * FS4 + ixm], wxp = s[2 * FS4 + ixp];
        const float4 wym = s[2 * FS4 + iym], wyp = s[2 * FS4 + iyp];
        const float4 wzm = zm_of(wc), wzp = zp_of(wc);
        const float4 lapW = lap3(wc, wxm, wxp, wym, wyp, wzm, wzp);
        const float4 advW = adv3(uc, vc, wc, wxm, wxp, wym, wyp, wzm, wzp);
        float4 dw = (lapW * MUc - dpdz) * rinv - advW;
        dw = make_float4(dw.x - Gc, dw.y - Gc, dw.z - Gc, dw.w - Gc);
        o[2 * FS4 + ic] = dw * m;
    }

    // ---- phase 5: c  (one-sided z at walls, NOT masked) ----
    {
        const float4 cc  = s[5 * FS4 + ic];
        const float4 cxm = s[5 * FS4 + ixm], cxp = s[5 * FS4 + ixp];
        const float4 cym = s[5 * FS4 + iym], cyp = s[5 * FS4 + iyp];
        const float4 czm = zm_of(cc), czp = zp_of(cc);

        float4 dcdz = (czp - czm) * inv2dz;
        if (lane == 0)  dcdz.x = (-3.0f * cc.x + 4.0f * cc.y - cc.z) * inv2dz;  // z=0: f0,f1,f2 local
        if (lane == 31) dcdz.w = ( 3.0f * cc.w - 4.0f * cc.z + cc.y) * inv2dz;  // z=127: local

        const float4 advC = uc * ((cxp - cxm) * inv2dx) + vc * ((cyp - cym) * inv2dy) + wc * dcdz;
        o[5 * FS4 + ic] = make_float4(-advC.x, -advC.y, -advC.z, -advC.w);
    }
}
} // namespace

extern "C" void kernel_launch(void* const* d_in, const int* in_sizes, int n_in,
                              void* d_out, int out_size)
{
    const float4* s = (const float4*)d_in[0];
    float4* o = (float4*)d_out;
    dim3 block(32, 8, 1);             // 256 threads: 32 z-chunks × 8 y
    dim3 grid(NY / 8, NX, 1);         // 32 × 256 blocks
    rb4_kernel<<<grid, block>>>(s, o);
}